// round 1
// baseline (speedup 1.0000x reference)
#include <cuda_runtime.h>
#include <math.h>

#define N     8192
#define D     256
#define H     512
#define KP    64            // prototypes
#define NT    17            // joint types
#define NSLOT (KP*NT)       // 1088
#define INV_TAU 20.0f       // 1/0.05
#define KLF  (1.0f/1.05f)   // RHO/(RHO+TAU)
#define SITERS 50
#define MAXNR 26            // max ceil(count/32) supported (count <= 832; mean 482, sd 21)

// ---------------- scratch (device globals; no allocation allowed) ----------------
__device__ float g_h[N*H];        // SELU(emb@W1+b1)
__device__ float g_hn[N];         // row norms^2 of h
__device__ float g_pn[KP];        // proto norms^2
__device__ float g_Mp[N*KP];      // M = -d2/tau, rows permuted by type, row-major
__device__ float g_MpT[KP*N];     // transposed copy (col pass coalescing)
__device__ float g_up[N];         // final log_u (permuted order)
__device__ float g_lv[NT*KP];     // final log_v per (type, k)
__device__ int   g_cnt[NT];
__device__ int   g_start[NT+1];
__device__ int   g_perm[N];       // permuted pos -> original row
__device__ int   g_pos[N];        // original row -> permuted pos

// ---------------- setup: type histogram + deterministic counting sort ------------
__global__ void k_init() {
    int i = threadIdx.x;
    if (i < NT) g_cnt[i] = 0;
}

__global__ void k_count(const int* __restrict__ jt) {
    int i = blockIdx.x * blockDim.x + threadIdx.x;
    if (i < N) atomicAdd(&g_cnt[jt[i]], 1);
}

__global__ void k_prefix() {
    if (threadIdx.x == 0) {
        int s = 0;
        for (int t = 0; t < NT; t++) { g_start[t] = s; s += g_cnt[t]; }
        g_start[NT] = s;
    }
}

// block t scans all rows in order; deterministic stable partition
__global__ void k_perm(const int* __restrict__ jt) {
    __shared__ int sc[256];
    __shared__ int run;
    int t = blockIdx.x, tid = threadIdx.x;
    if (tid == 0) run = g_start[t];
    __syncthreads();
    for (int base = 0; base < N; base += 256) {
        int n = base + tid;
        int f = (jt[n] == t) ? 1 : 0;
        sc[tid] = f;
        __syncthreads();
        // Hillis-Steele inclusive scan
        for (int off = 1; off < 256; off <<= 1) {
            int v = 0;
            if (tid >= off) v = sc[tid - off];
            __syncthreads();
            if (tid >= off) sc[tid] += v;
            __syncthreads();
        }
        if (f) {
            int p = run + sc[tid] - 1;
            g_perm[p] = n;
            g_pos[n]  = p;
        }
        __syncthreads();
        if (tid == 0) run += sc[255];
        __syncthreads();
    }
}

// ---------------- GEMM1: h = selu(emb @ W1 + b1), fp32 --------------------------
// BM=128, BN=64, BK=16, 256 threads, 8x4 microtile
__global__ void k_gemm1(const float* __restrict__ A, const float* __restrict__ W,
                        const float* __restrict__ bias) {
    __shared__ float As[128][17];
    __shared__ __align__(16) float Bs[16][64];
    int bm = blockIdx.x * 128, bn = blockIdx.y * 64;
    int tid = threadIdx.x;
    int ty = tid >> 4, tx = tid & 15;

    float acc[8][4];
#pragma unroll
    for (int i = 0; i < 8; i++)
#pragma unroll
        for (int j = 0; j < 4; j++) acc[i][j] = 0.f;

    for (int k0 = 0; k0 < D; k0 += 16) {
#pragma unroll
        for (int i = 0; i < 8; i++) {
            int e = tid + i * 256;
            int r = e >> 4, c = e & 15;
            As[r][c] = A[(bm + r) * D + k0 + c];
        }
#pragma unroll
        for (int i = 0; i < 4; i++) {
            int e = tid + i * 256;
            int r = e >> 6, c = e & 63;
            Bs[r][c] = W[(k0 + r) * H + bn + c];
        }
        __syncthreads();
#pragma unroll
        for (int kk = 0; kk < 16; kk++) {
            float4 bv = *(const float4*)&Bs[kk][tx * 4];
            float bf[4] = {bv.x, bv.y, bv.z, bv.w};
#pragma unroll
            for (int i = 0; i < 8; i++) {
                float a = As[ty * 8 + i][kk];
#pragma unroll
                for (int j = 0; j < 4; j++) acc[i][j] += a * bf[j];
            }
        }
        __syncthreads();
    }
    const float SC = 1.0507009873554805f;
    const float AL = 1.6732632423543772f;
#pragma unroll
    for (int i = 0; i < 8; i++) {
        int row = bm + ty * 8 + i;
#pragma unroll
        for (int j = 0; j < 4; j++) {
            int col = bn + tx * 4 + j;
            float x = acc[i][j] + bias[col];
            float s = (x > 0.f) ? SC * x : SC * AL * expm1f(x);
            g_h[row * H + col] = s;
        }
    }
}

// row norms of h: one warp per row
__global__ void k_hn() {
    int gw = (blockIdx.x * blockDim.x + threadIdx.x) >> 5;
    int lane = threadIdx.x & 31;
    if (gw >= N) return;
    const float* row = &g_h[gw * H];
    float s = 0.f;
#pragma unroll
    for (int j = 0; j < H / 32; j++) {
        float v = row[lane + j * 32];
        s += v * v;
    }
#pragma unroll
    for (int o = 16; o; o >>= 1) s += __shfl_xor_sync(0xffffffffu, s, o);
    if (lane == 0) g_hn[gw] = s;
}

__global__ void k_pn(const float* __restrict__ proto) {
    int w = threadIdx.x >> 5, lane = threadIdx.x & 31;
    for (int r = w; r < KP; r += 8) {
        const float* row = &proto[r * H];
        float s = 0.f;
#pragma unroll
        for (int j = 0; j < H / 32; j++) {
            float v = row[lane + j * 32];
            s += v * v;
        }
#pragma unroll
        for (int o = 16; o; o >>= 1) s += __shfl_xor_sync(0xffffffffu, s, o);
        if (lane == 0) g_pn[r] = s;
    }
}

// ---------------- GEMM2: d2 -> M = -d2/tau (permuted, both layouts) -------------
// BM=128, BN=64(=KP), BK=32, 256 threads, 8x4 microtile
__global__ void k_gemm2(const float* __restrict__ proto) {
    __shared__ float Hs[128][33];
    __shared__ float Ps[64][33];
    int bm = blockIdx.x * 128;
    int tid = threadIdx.x;
    int ty = tid >> 4, tx = tid & 15;

    float acc[8][4];
#pragma unroll
    for (int i = 0; i < 8; i++)
#pragma unroll
        for (int j = 0; j < 4; j++) acc[i][j] = 0.f;

    for (int j0 = 0; j0 < H; j0 += 32) {
#pragma unroll
        for (int i = 0; i < 16; i++) {
            int e = tid + i * 256;
            int r = e >> 5, c = e & 31;
            Hs[r][c] = g_h[(bm + r) * H + j0 + c];
        }
#pragma unroll
        for (int i = 0; i < 8; i++) {
            int e = tid + i * 256;
            int r = e >> 5, c = e & 31;
            Ps[r][c] = proto[r * H + j0 + c];
        }
        __syncthreads();
#pragma unroll
        for (int kk = 0; kk < 32; kk++) {
            float bf[4];
#pragma unroll
            for (int j = 0; j < 4; j++) bf[j] = Ps[tx * 4 + j][kk];
#pragma unroll
            for (int i = 0; i < 8; i++) {
                float a = Hs[ty * 8 + i][kk];
#pragma unroll
                for (int j = 0; j < 4; j++) acc[i][j] += a * bf[j];
            }
        }
        __syncthreads();
    }
#pragma unroll
    for (int i = 0; i < 8; i++) {
        int n = bm + ty * 8 + i;
        float hn = g_hn[n];
        int p = g_pos[n];
#pragma unroll
        for (int j = 0; j < 4; j++) {
            int k = tx * 4 + j;
            float d2 = hn + g_pn[k] - 2.f * acc[i][j];
            d2 = fmaxf(d2, 0.f);
            float m = -INV_TAU * d2;
            g_Mp[p * KP + k]  = m;
            g_MpT[k * N + p]  = m;
        }
    }
}

// ---------------- Sinkhorn: 17 independent CTAs, 50 iterations ------------------
__global__ void __launch_bounds__(512) k_sinkhorn() {
    __shared__ float su[MAXNR * 32];   // log_u for this type's rows
    __shared__ float slv[KP];          // log_v for this type's 64 slots
    int t = blockIdx.x;
    int s = g_start[t], e = g_start[t + 1];
    int c = e - s;
    int tid = threadIdx.x, w = tid >> 5, lane = tid & 31;

    if (tid < KP) slv[tid] = 0.f;
    __syncthreads();

    for (int it = 0; it < SITERS; it++) {
        // ---- row update: log_u[r] = -logsumexp_k(M[r,k] + lv[k])
        float lv0 = slv[lane], lv1 = slv[lane + 32];
        for (int r = w; r < c; r += 16) {
            const float* row = &g_Mp[(s + r) * KP];
            float v0 = row[lane] + lv0;
            float v1 = row[lane + 32] + lv1;
            float mx = fmaxf(v0, v1);
#pragma unroll
            for (int o = 16; o; o >>= 1) mx = fmaxf(mx, __shfl_xor_sync(0xffffffffu, mx, o));
            float se = __expf(v0 - mx) + __expf(v1 - mx);
#pragma unroll
            for (int o = 16; o; o >>= 1) se += __shfl_xor_sync(0xffffffffu, se, o);
            if (lane == 0) su[r] = -(mx + __logf(se));
        }
        __syncthreads();

        // ---- col update: lv[k] = -KLF * logsumexp_r(M[r,k] + u[r])
        for (int k = w; k < KP; k += 16) {
            const float* colM = &g_MpT[k * N + s];
            float vals[MAXNR];
            float mx = -3.4e38f;
#pragma unroll
            for (int i = 0; i < MAXNR; i++) {
                if (i * 32 >= c) break;
                int r = lane + i * 32;
                float v = -3.4e38f;
                if (r < c) v = colM[r] + su[r];
                vals[i] = v;
                mx = fmaxf(mx, v);
            }
#pragma unroll
            for (int o = 16; o; o >>= 1) mx = fmaxf(mx, __shfl_xor_sync(0xffffffffu, mx, o));
            float se = 0.f;
#pragma unroll
            for (int i = 0; i < MAXNR; i++) {
                if (i * 32 >= c) break;
                se += __expf(vals[i] - mx);
            }
#pragma unroll
            for (int o = 16; o; o >>= 1) se += __shfl_xor_sync(0xffffffffu, se, o);
            if (lane == 0) slv[k] = -KLF * (mx + __logf(se));
        }
        __syncthreads();
    }

    for (int r = tid; r < c; r += 512) g_up[s + r] = su[r];
    if (tid < KP) g_lv[t * KP + tid] = slv[tid];
}

// ---------------- outputs -------------------------------------------------------
__global__ void k_zeroT(float* __restrict__ outT) {
    int i = blockIdx.x * blockDim.x + threadIdx.x;
    if (i < (N * NSLOT) / 4) ((float4*)outT)[i] = make_float4(0.f, 0.f, 0.f, 0.f);
}

__global__ void k_final(const int* __restrict__ jt, float* __restrict__ out, int write_T) {
    int idx = blockIdx.x * blockDim.x + threadIdx.x;
    if (idx >= N * KP) return;
    int p = idx >> 6, k = idx & 63;
    int orig = g_perm[p];
    int t = jt[orig];
    float val = g_Mp[idx] + g_up[p] + g_lv[t * KP + k];
    float pm = __expf(val);
    out[orig * KP + k] = __logf(pm + 1e-8f);                    // logits
    if (write_T) out[N * KP + orig * NSLOT + k * NT + t] = pm;  // T (valid slot only)
}

// ---------------- launch --------------------------------------------------------
extern "C" void kernel_launch(void* const* d_in, const int* in_sizes, int n_in,
                              void* d_out, int out_size) {
    const float* emb   = (const float*)d_in[0];
    const int*   jt    = (const int*)d_in[1];
    const float* W1    = (const float*)d_in[2];
    const float* b1    = (const float*)d_in[3];
    const float* proto = (const float*)d_in[4];
    float* out = (float*)d_out;
    int write_T = (out_size >= N * KP + N * NSLOT) ? 1 : 0;

    k_init<<<1, 32>>>();
    k_count<<<(N + 255) / 256, 256>>>(jt);
    k_prefix<<<1, 1>>>();
    k_perm<<<NT, 256>>>(jt);

    k_gemm1<<<dim3(N / 128, H / 64), 256>>>(emb, W1, b1);
    k_hn<<<(N * 32) / 256, 256>>>();
    k_pn<<<1, 256>>>(proto);
    k_gemm2<<<N / 128, 256>>>(proto);

    k_sinkhorn<<<NT, 512>>>();

    if (write_T) k_zeroT<<<((N * NSLOT) / 4 + 255) / 256, 256>>>(out + N * KP);
    k_final<<<(N * KP) / 256, 256>>>(jt, out, write_T);
}

// round 2
// speedup vs baseline: 5.0155x; 5.0155x over previous
#include <cuda_runtime.h>
#include <math.h>

#define N     8192
#define D     256
#define H     512
#define KP    64            // prototypes
#define NT    17            // joint types
#define NSLOT (KP*NT)       // 1088
#define INV_TAU 20.0f       // 1/0.05
#define KLF  (1.0f/1.05f)   // RHO/(RHO+TAU)
#define SITERS 50
#define CSIZE 8             // cluster size (CTAs per joint type)
#define MAXC  768           // max rows per type supported (mean 482, sd 21 -> +13 sigma)
#define MAXCHUNK 96         // MAXC / CSIZE

// ---------------- scratch (device globals; no allocation allowed) ----------------
__device__ float g_h[N*H];        // SELU(emb@W1+b1)
__device__ float g_hn[N];         // row norms^2 of h
__device__ float g_pn[KP];        // proto norms^2
__device__ float g_Mp[N*KP];      // M = -d2/tau, rows permuted by type, row-major
__device__ float g_up[N];         // final log_u (permuted order)
__device__ float g_lv[NT*KP];     // final log_v per (type, k)
__device__ int   g_cnt[NT];
__device__ int   g_start[NT+1];
__device__ int   g_perm[N];       // permuted pos -> original row
__device__ int   g_pos[N];        // original row -> permuted pos

// ---------------- helpers -------------------------------------------------------
__device__ __forceinline__ unsigned smem_u32(const void* p) {
    unsigned a;
    asm("{ .reg .u64 t; cvta.to.shared.u64 t, %1; cvt.u32.u64 %0, t; }" : "=r"(a) : "l"(p));
    return a;
}
__device__ __forceinline__ float dsmem_ldf(unsigned laddr, unsigned rank) {
    unsigned r; float v;
    asm volatile("mapa.shared::cluster.u32 %0, %1, %2;" : "=r"(r) : "r"(laddr), "r"(rank));
    asm volatile("ld.shared::cluster.f32 %0, [%1];" : "=f"(v) : "r"(r));
    return v;
}

// ---------------- setup: type histogram + deterministic counting sort ------------
__global__ void k_init() {
    int i = threadIdx.x;
    if (i < NT) g_cnt[i] = 0;
}

__global__ void k_count(const int* __restrict__ jt) {
    int i = blockIdx.x * blockDim.x + threadIdx.x;
    if (i < N) atomicAdd(&g_cnt[jt[i]], 1);
}

__global__ void k_prefix() {
    if (threadIdx.x == 0) {
        int s = 0;
        for (int t = 0; t < NT; t++) { g_start[t] = s; s += g_cnt[t]; }
        g_start[NT] = s;
    }
}

// single-CTA stable counting sort via warp-aggregated match_any
__global__ void __launch_bounds__(1024) k_perm2(const int* __restrict__ jt) {
    __shared__ int run[NT];
    __shared__ int tot[NT];
    __shared__ int hist[32*NT];
    __shared__ int woff[32*NT];
    int tid = threadIdx.x, w = tid >> 5, lane = tid & 31;
    if (tid < NT) run[tid] = g_start[tid];
    for (int base = 0; base < N; base += 1024) {
        if (tid < 32*NT) hist[tid] = 0;
        __syncthreads();
        int n = base + tid;
        int t = jt[n];
        unsigned mask = __match_any_sync(0xffffffffu, t);
        int rnk = __popc(mask & ((1u << lane) - 1u));
        if (rnk == 0) hist[w*NT + t] = __popc(mask);
        __syncthreads();
        if (tid < NT) {
            int ssum = 0;
            for (int ww = 0; ww < 32; ww++) { woff[ww*NT + tid] = ssum; ssum += hist[ww*NT + tid]; }
            tot[tid] = ssum;
        }
        __syncthreads();
        int pos = run[t] + woff[w*NT + t] + rnk;
        g_perm[pos] = n;
        g_pos[n]  = pos;
        __syncthreads();
        if (tid < NT) run[tid] += tot[tid];
        // run update is ordered before next chunk's read by the first sync of next chunk
    }
}

// ---------------- GEMM1: h = selu(emb @ W1 + b1), fp32 --------------------------
__global__ void k_gemm1(const float* __restrict__ A, const float* __restrict__ W,
                        const float* __restrict__ bias) {
    __shared__ float As[128][17];
    __shared__ __align__(16) float Bs[16][64];
    int bm = blockIdx.x * 128, bn = blockIdx.y * 64;
    int tid = threadIdx.x;
    int ty = tid >> 4, tx = tid & 15;

    float acc[8][4];
#pragma unroll
    for (int i = 0; i < 8; i++)
#pragma unroll
        for (int j = 0; j < 4; j++) acc[i][j] = 0.f;

    for (int k0 = 0; k0 < D; k0 += 16) {
#pragma unroll
        for (int i = 0; i < 8; i++) {
            int e = tid + i * 256;
            int r = e >> 4, c = e & 15;
            As[r][c] = A[(bm + r) * D + k0 + c];
        }
#pragma unroll
        for (int i = 0; i < 4; i++) {
            int e = tid + i * 256;
            int r = e >> 6, c = e & 63;
            Bs[r][c] = W[(k0 + r) * H + bn + c];
        }
        __syncthreads();
#pragma unroll
        for (int kk = 0; kk < 16; kk++) {
            float4 bv = *(const float4*)&Bs[kk][tx * 4];
            float bf[4] = {bv.x, bv.y, bv.z, bv.w};
#pragma unroll
            for (int i = 0; i < 8; i++) {
                float a = As[ty * 8 + i][kk];
#pragma unroll
                for (int j = 0; j < 4; j++) acc[i][j] += a * bf[j];
            }
        }
        __syncthreads();
    }
    const float SC = 1.0507009873554805f;
    const float AL = 1.6732632423543772f;
#pragma unroll
    for (int i = 0; i < 8; i++) {
        int row = bm + ty * 8 + i;
#pragma unroll
        for (int j = 0; j < 4; j++) {
            int col = bn + tx * 4 + j;
            float x = acc[i][j] + bias[col];
            float s = (x > 0.f) ? SC * x : SC * AL * expm1f(x);
            g_h[row * H + col] = s;
        }
    }
}

// row norms of h: one warp per row
__global__ void k_hn() {
    int gw = (blockIdx.x * blockDim.x + threadIdx.x) >> 5;
    int lane = threadIdx.x & 31;
    if (gw >= N) return;
    const float* row = &g_h[gw * H];
    float s = 0.f;
#pragma unroll
    for (int j = 0; j < H / 32; j++) {
        float v = row[lane + j * 32];
        s += v * v;
    }
#pragma unroll
    for (int o = 16; o; o >>= 1) s += __shfl_xor_sync(0xffffffffu, s, o);
    if (lane == 0) g_hn[gw] = s;
}

__global__ void k_pn(const float* __restrict__ proto) {
    int w = threadIdx.x >> 5, lane = threadIdx.x & 31;
    for (int r = w; r < KP; r += 8) {
        const float* row = &proto[r * H];
        float s = 0.f;
#pragma unroll
        for (int j = 0; j < H / 32; j++) {
            float v = row[lane + j * 32];
            s += v * v;
        }
#pragma unroll
        for (int o = 16; o; o >>= 1) s += __shfl_xor_sync(0xffffffffu, s, o);
        if (lane == 0) g_pn[r] = s;
    }
}

// ---------------- GEMM2: d2 -> M = -d2/tau (permuted row-major) -----------------
__global__ void k_gemm2(const float* __restrict__ proto) {
    __shared__ float Hs[128][33];
    __shared__ float Ps[64][33];
    int bm = blockIdx.x * 128;
    int tid = threadIdx.x;
    int ty = tid >> 4, tx = tid & 15;

    float acc[8][4];
#pragma unroll
    for (int i = 0; i < 8; i++)
#pragma unroll
        for (int j = 0; j < 4; j++) acc[i][j] = 0.f;

    for (int j0 = 0; j0 < H; j0 += 32) {
#pragma unroll
        for (int i = 0; i < 16; i++) {
            int e = tid + i * 256;
            int r = e >> 5, c = e & 31;
            Hs[r][c] = g_h[(bm + r) * H + j0 + c];
        }
#pragma unroll
        for (int i = 0; i < 8; i++) {
            int e = tid + i * 256;
            int r = e >> 5, c = e & 31;
            Ps[r][c] = proto[r * H + j0 + c];
        }
        __syncthreads();
#pragma unroll
        for (int kk = 0; kk < 32; kk++) {
            float bf[4];
#pragma unroll
            for (int j = 0; j < 4; j++) bf[j] = Ps[tx * 4 + j][kk];
#pragma unroll
            for (int i = 0; i < 8; i++) {
                float a = Hs[ty * 8 + i][kk];
#pragma unroll
                for (int j = 0; j < 4; j++) acc[i][j] += a * bf[j];
            }
        }
        __syncthreads();
    }
#pragma unroll
    for (int i = 0; i < 8; i++) {
        int n = bm + ty * 8 + i;
        float hn = g_hn[n];
        int p = g_pos[n];
#pragma unroll
        for (int j = 0; j < 4; j++) {
            int k = tx * 4 + j;
            float d2 = hn + g_pn[k] - 2.f * acc[i][j];
            d2 = fmaxf(d2, 0.f);
            g_Mp[p * KP + k] = -INV_TAU * d2;
        }
    }
}

// ---------------- Sinkhorn: 17 types x 8-CTA clusters, M resident in smem -------
__global__ void __cluster_dims__(CSIZE, 1, 1) __launch_bounds__(256)
k_sinkhorn() {
    __shared__ float sM[MAXCHUNK * 65];     // padded: conflict-free rows AND cols
    __shared__ float su[MAXCHUNK];
    __shared__ float slv[KP];
    __shared__ float wmx[4][KP], wse[4][KP];
    __shared__ float pmx[2][KP], pse[2][KP];  // double-buffered cluster partials

    int t    = blockIdx.x >> 3;
    int rank = blockIdx.x & 7;
    int s = g_start[t];
    int c = g_start[t + 1] - s;
    int chunk = (c + CSIZE - 1) >> 3;
    int r0 = rank * chunk;
    int cn = c - r0;
    if (cn < 0) cn = 0;
    if (cn > chunk) cn = chunk;
    int tid = threadIdx.x, w = tid >> 5, lane = tid & 31;

    // load this CTA's M slice into smem (coalesced gmem, padded smem)
    for (int idx = tid; idx < cn * KP; idx += 256) {
        int r = idx >> 6, col = idx & 63;
        sM[r * 65 + col] = g_Mp[(s + r0 + r) * KP + col];
    }
    if (tid < KP) slv[tid] = 0.f;
    __syncthreads();

    int q = (cn + 3) >> 2;   // rows per column-pass sub-chunk

    for (int it = 0; it < SITERS; it++) {
        // ---- row update: su[r] = -lse_k(M[r,k] + lv[k])   (lane-serial, no shuffles)
        if (tid < cn) {
            const float* row = &sM[tid * 65];
            float mx = -3.4e38f;
#pragma unroll 8
            for (int j = 0; j < KP; j++) mx = fmaxf(mx, row[j] + slv[j]);
            float se = 0.f;
#pragma unroll 8
            for (int j = 0; j < KP; j++) se += __expf(row[j] + slv[j] - mx);
            su[tid] = -(mx + __logf(se));
        }
        __syncthreads();

        // ---- column partials over local rows: warp w -> cols 32*(w&1)+lane, sub-chunk w>>1
        {
            int col = ((w & 1) << 5) + lane;
            int rs_ = (w >> 1) * q;
            int re_ = min(cn, rs_ + q);
            float mx = -3.4e38f;
            for (int r = rs_; r < re_; r++) mx = fmaxf(mx, sM[r * 65 + col] + su[r]);
            float se = 0.f;
            for (int r = rs_; r < re_; r++) se += __expf(sM[r * 65 + col] + su[r] - mx);
            wmx[w >> 1][col] = mx;
            wse[w >> 1][col] = se;
        }
        __syncthreads();
        int par = it & 1;
        if (tid < KP) {
            float mx = wmx[0][tid];
            mx = fmaxf(mx, wmx[1][tid]);
            mx = fmaxf(mx, wmx[2][tid]);
            mx = fmaxf(mx, wmx[3][tid]);
            float se = 0.f;
#pragma unroll
            for (int i = 0; i < 4; i++) se += wse[i][tid] * __expf(wmx[i][tid] - mx);
            pmx[par][tid] = mx;
            pse[par][tid] = se;
        }

        // ---- one cluster sync per iteration (partials double-buffered)
        asm volatile("barrier.cluster.arrive.aligned;" ::: "memory");
        asm volatile("barrier.cluster.wait.aligned;" ::: "memory");

        // ---- combine partials from all 8 ranks via DSMEM; every CTA computes lv
        if (tid < KP) {
            unsigned amx = smem_u32(&pmx[par][tid]);
            unsigned ase = smem_u32(&pse[par][tid]);
            float m[CSIZE], sv[CSIZE];
            float MX = -3.4e38f;
#pragma unroll
            for (int rk = 0; rk < CSIZE; rk++) {
                m[rk]  = dsmem_ldf(amx, rk);
                sv[rk] = dsmem_ldf(ase, rk);
                MX = fmaxf(MX, m[rk]);
            }
            float SE = 0.f;
#pragma unroll
            for (int rk = 0; rk < CSIZE; rk++) SE += sv[rk] * __expf(m[rk] - MX);
            slv[tid] = -KLF * (MX + __logf(SE));
        }
        __syncthreads();
    }

    if (tid < cn) g_up[s + r0 + tid] = su[tid];
    if (rank == 0 && tid < KP) g_lv[t * KP + tid] = slv[tid];
}

// ---------------- outputs -------------------------------------------------------
__global__ void k_zeroT(float* __restrict__ outT) {
    int i = blockIdx.x * blockDim.x + threadIdx.x;
    if (i < (N * NSLOT) / 4) ((float4*)outT)[i] = make_float4(0.f, 0.f, 0.f, 0.f);
}

__global__ void k_final(const int* __restrict__ jt, float* __restrict__ out, int write_T) {
    int idx = blockIdx.x * blockDim.x + threadIdx.x;
    if (idx >= N * KP) return;
    int p = idx >> 6, k = idx & 63;
    int orig = g_perm[p];
    int t = jt[orig];
    float val = g_Mp[idx] + g_up[p] + g_lv[t * KP + k];
    float pm = __expf(val);
    out[orig * KP + k] = __logf(pm + 1e-8f);                    // logits
    if (write_T) out[N * KP + orig * NSLOT + k * NT + t] = pm;  // T (valid slot only)
}

// ---------------- launch --------------------------------------------------------
extern "C" void kernel_launch(void* const* d_in, const int* in_sizes, int n_in,
                              void* d_out, int out_size) {
    const float* emb   = (const float*)d_in[0];
    const int*   jt    = (const int*)d_in[1];
    const float* W1    = (const float*)d_in[2];
    const float* b1    = (const float*)d_in[3];
    const float* proto = (const float*)d_in[4];
    float* out = (float*)d_out;
    int write_T = (out_size >= N * KP + N * NSLOT) ? 1 : 0;

    k_init<<<1, 32>>>();
    k_count<<<(N + 255) / 256, 256>>>(jt);
    k_prefix<<<1, 1>>>();
    k_perm2<<<1, 1024>>>(jt);

    k_gemm1<<<dim3(N / 128, H / 64), 256>>>(emb, W1, b1);
    k_hn<<<(N * 32) / 256, 256>>>();
    k_pn<<<1, 256>>>(proto);
    k_gemm2<<<N / 128, 256>>>(proto);

    k_sinkhorn<<<NT * CSIZE, 256>>>();

    if (write_T) k_zeroT<<<((N * NSLOT) / 4 + 255) / 256, 256>>>(out + N * KP);
    k_final<<<(N * KP) / 256, 256>>>(jt, out, write_T);
}

// round 4
// speedup vs baseline: 5.7181x; 1.1401x over previous
#include <cuda_runtime.h>
#include <math.h>

#define N     8192
#define D     256
#define H     512
#define KP    64
#define NT    17
#define NSLOT (KP*NT)       // 1088
#define INV_TAU 20.0f
#define KLF  (1.0f/1.05f)
#define SITERS 50
#define CSIZE 8
#define MAXC  768
#define MAXCHUNK 96
#define NBH   32            // histogram blocks (N/256)

// ---------------- scratch ----------------
__device__ float g_h[N*H];
__device__ float g_Mp[N*KP];      // M = -d2/tau, rows permuted by type
__device__ float g_up[N];
__device__ float g_lv[NT*KP];
__device__ int   g_start[NT+1];
__device__ int   g_perm[N];
__device__ int   g_pos[N];
__device__ int   g_bh[NBH*NT];    // per-block type histograms
__device__ int   g_off[NBH*NT];   // per-block scatter bases

// ---------------- helpers ----------------
__device__ __forceinline__ unsigned smem_u32(const void* p) {
    unsigned a;
    asm("{ .reg .u64 t; cvta.to.shared.u64 t, %1; cvt.u32.u64 %0, t; }" : "=r"(a) : "l"(p));
    return a;
}
__device__ __forceinline__ float dsmem_ldf(unsigned laddr, unsigned rank) {
    unsigned r; float v;
    asm volatile("mapa.shared::cluster.u32 %0, %1, %2;" : "=r"(r) : "r"(laddr), "r"(rank));
    asm volatile("ld.shared::cluster.f32 %0, [%1];" : "=f"(v) : "r"(r));
    return v;
}

// ---------------- parallel stable counting sort ----------------
__global__ void p_hist(const int* __restrict__ jt) {
    __shared__ int h[8][NT];
    int tid = threadIdx.x, w = tid >> 5, lane = tid & 31, b = blockIdx.x;
    if (tid < 8 * NT) ((int*)h)[tid] = 0;
    __syncthreads();
    int t = jt[b * 256 + tid];
    unsigned mask = __match_any_sync(0xffffffffu, t);
    int rnk = __popc(mask & ((1u << lane) - 1u));
    if (rnk == 0) h[w][t] = __popc(mask);
    __syncthreads();
    if (tid < NT) {
        int s = 0;
#pragma unroll
        for (int ww = 0; ww < 8; ww++) s += h[ww][tid];
        g_bh[b * NT + tid] = s;
    }
}

__global__ void p_scan() {
    __shared__ int cnt[NT];
    int tid = threadIdx.x;
    if (tid < NT) {
        int s = 0;
        for (int b = 0; b < NBH; b++) s += g_bh[b * NT + tid];
        cnt[tid] = s;
    }
    __syncthreads();
    if (tid == 0) {
        int s = 0;
        for (int t = 0; t < NT; t++) { g_start[t] = s; s += cnt[t]; }
        g_start[NT] = s;
    }
    __syncthreads();
    if (tid < NT) {
        int run = g_start[tid];
        for (int b = 0; b < NBH; b++) { g_off[b * NT + tid] = run; run += g_bh[b * NT + tid]; }
    }
}

__global__ void p_scatter(const int* __restrict__ jt) {
    __shared__ int h[8][NT];
    __shared__ int off[8][NT];
    int tid = threadIdx.x, w = tid >> 5, lane = tid & 31, b = blockIdx.x;
    if (tid < 8 * NT) ((int*)h)[tid] = 0;
    __syncthreads();
    int n = b * 256 + tid;
    int t = jt[n];
    unsigned mask = __match_any_sync(0xffffffffu, t);
    int rnk = __popc(mask & ((1u << lane) - 1u));
    if (rnk == 0) h[w][t] = __popc(mask);
    __syncthreads();
    if (tid < NT) {
        int run = g_off[b * NT + tid];
#pragma unroll
        for (int ww = 0; ww < 8; ww++) { off[ww][tid] = run; run += h[ww][tid]; }
    }
    __syncthreads();
    int pos = off[w][t] + rnk;
    g_perm[pos] = n;
    g_pos[n]  = pos;
}

// ---------------- GEMM1: h = selu(emb @ W1 + b1) -------------------------------
// 128x128 tile, BK=32, 256 threads, 8x8 microtile, k-major smem
__global__ void __launch_bounds__(256) k_gemm1(const float* __restrict__ A,
                                               const float* __restrict__ W,
                                               const float* __restrict__ bias) {
    __shared__ __align__(16) float As[32][132];
    __shared__ __align__(16) float Bs[32][128];
    __shared__ float sb[128];
    int bm = blockIdx.x * 128, bn = blockIdx.y * 128;
    int tid = threadIdx.x;
    int ty = tid >> 4, tx = tid & 15;
    if (tid < 128) sb[tid] = bias[bn + tid];

    float acc[8][8];
#pragma unroll
    for (int i = 0; i < 8; i++)
#pragma unroll
        for (int j = 0; j < 8; j++) acc[i][j] = 0.f;

    for (int k0 = 0; k0 < D; k0 += 32) {
#pragma unroll
        for (int i = 0; i < 4; i++) {
            int idx = tid + i * 256;
            int r = idx >> 3, c4 = idx & 7;
            float4 v = *(const float4*)&A[(bm + r) * D + k0 + c4 * 4];
            As[c4 * 4 + 0][r] = v.x;
            As[c4 * 4 + 1][r] = v.y;
            As[c4 * 4 + 2][r] = v.z;
            As[c4 * 4 + 3][r] = v.w;
        }
#pragma unroll
        for (int i = 0; i < 4; i++) {
            int idx = tid + i * 256;
            int k = idx >> 5, n4 = idx & 31;
            *(float4*)&Bs[k][n4 * 4] = *(const float4*)&W[(k0 + k) * H + bn + n4 * 4];
        }
        __syncthreads();
#pragma unroll
        for (int kk = 0; kk < 32; kk++) {
            float4 a0 = *(const float4*)&As[kk][ty * 8];
            float4 a1 = *(const float4*)&As[kk][ty * 8 + 4];
            float4 b0 = *(const float4*)&Bs[kk][tx * 8];
            float4 b1 = *(const float4*)&Bs[kk][tx * 8 + 4];
            float av[8] = {a0.x, a0.y, a0.z, a0.w, a1.x, a1.y, a1.z, a1.w};
            float bv[8] = {b0.x, b0.y, b0.z, b0.w, b1.x, b1.y, b1.z, b1.w};
#pragma unroll
            for (int i = 0; i < 8; i++)
#pragma unroll
                for (int j = 0; j < 8; j++) acc[i][j] += av[i] * bv[j];
        }
        __syncthreads();
    }
    const float SC = 1.0507009873554805f;
    const float AL = 1.6732632423543772f;
#pragma unroll
    for (int i = 0; i < 8; i++) {
        int row = bm + ty * 8 + i;
        float o[8];
#pragma unroll
        for (int j = 0; j < 8; j++) {
            float x = acc[i][j] + sb[tx * 8 + j];
            o[j] = (x > 0.f) ? SC * x : SC * AL * expm1f(x);
        }
        *(float4*)&g_h[row * H + bn + tx * 8]     = make_float4(o[0], o[1], o[2], o[3]);
        *(float4*)&g_h[row * H + bn + tx * 8 + 4] = make_float4(o[4], o[5], o[6], o[7]);
    }
}

// ---------------- GEMM2: d2 -> M, fused h/proto norms ---------------------------
// BM=64, BN=64, BK=32, 256 threads (16x16), 4x4 microtile, 128 CTAs
__global__ void __launch_bounds__(256) k_gemm2(const float* __restrict__ proto) {
    __shared__ __align__(16) float Hs[32][68];
    __shared__ __align__(16) float Ps[32][68];
    __shared__ float shn[64];
    __shared__ float spn[64];
    int bm = blockIdx.x * 64;
    int tid = threadIdx.x;
    int ty = tid >> 4, tx = tid & 15;
    int lr = tid >> 3, lc = tid & 7;

    float acc[4][4];
#pragma unroll
    for (int i = 0; i < 4; i++)
#pragma unroll
        for (int j = 0; j < 4; j++) acc[i][j] = 0.f;
    float hn0 = 0.f, hn1 = 0.f, pn0 = 0.f, pn1 = 0.f;

    for (int j0 = 0; j0 < H; j0 += 32) {
        {
            float4 v = *(const float4*)&g_h[(bm + lr) * H + j0 + lc * 4];
            Hs[lc * 4 + 0][lr] = v.x; Hs[lc * 4 + 1][lr] = v.y;
            Hs[lc * 4 + 2][lr] = v.z; Hs[lc * 4 + 3][lr] = v.w;
            hn0 += v.x * v.x + v.y * v.y + v.z * v.z + v.w * v.w;
            float4 u = *(const float4*)&g_h[(bm + lr + 32) * H + j0 + lc * 4];
            Hs[lc * 4 + 0][lr + 32] = u.x; Hs[lc * 4 + 1][lr + 32] = u.y;
            Hs[lc * 4 + 2][lr + 32] = u.z; Hs[lc * 4 + 3][lr + 32] = u.w;
            hn1 += u.x * u.x + u.y * u.y + u.z * u.z + u.w * u.w;
        }
        {
            float4 v = *(const float4*)&proto[lr * H + j0 + lc * 4];
            Ps[lc * 4 + 0][lr] = v.x; Ps[lc * 4 + 1][lr] = v.y;
            Ps[lc * 4 + 2][lr] = v.z; Ps[lc * 4 + 3][lr] = v.w;
            pn0 += v.x * v.x + v.y * v.y + v.z * v.z + v.w * v.w;
            float4 u = *(const float4*)&proto[(lr + 32) * H + j0 + lc * 4];
            Ps[lc * 4 + 0][lr + 32] = u.x; Ps[lc * 4 + 1][lr + 32] = u.y;
            Ps[lc * 4 + 2][lr + 32] = u.z; Ps[lc * 4 + 3][lr + 32] = u.w;
            pn1 += u.x * u.x + u.y * u.y + u.z * u.z + u.w * u.w;
        }
        __syncthreads();
#pragma unroll
        for (int kk = 0; kk < 32; kk++) {
            float4 a = *(const float4*)&Hs[kk][ty * 4];
            float4 b = *(const float4*)&Ps[kk][tx * 4];
            float av[4] = {a.x, a.y, a.z, a.w};
            float bv[4] = {b.x, b.y, b.z, b.w};
#pragma unroll
            for (int i = 0; i < 4; i++)
#pragma unroll
                for (int j = 0; j < 4; j++) acc[i][j] += av[i] * bv[j];
        }
        __syncthreads();
    }
#pragma unroll
    for (int o = 1; o < 8; o <<= 1) {
        hn0 += __shfl_xor_sync(0xffffffffu, hn0, o);
        hn1 += __shfl_xor_sync(0xffffffffu, hn1, o);
        pn0 += __shfl_xor_sync(0xffffffffu, pn0, o);
        pn1 += __shfl_xor_sync(0xffffffffu, pn1, o);
    }
    if (lc == 0) { shn[lr] = hn0; shn[lr + 32] = hn1; spn[lr] = pn0; spn[lr + 32] = pn1; }
    __syncthreads();

#pragma unroll
    for (int i = 0; i < 4; i++) {
        int n = bm + ty * 4 + i;
        float hn = shn[ty * 4 + i];
        int p = g_pos[n];
        float o[4];
#pragma unroll
        for (int j = 0; j < 4; j++) {
            float d2 = hn + spn[tx * 4 + j] - 2.f * acc[i][j];
            o[j] = -INV_TAU * fmaxf(d2, 0.f);
        }
        *(float4*)&g_Mp[p * KP + tx * 4] = make_float4(o[0], o[1], o[2], o[3]);
    }
}

// ---------------- Sinkhorn: 17 types x 8-CTA clusters ---------------------------
__global__ void __cluster_dims__(CSIZE, 1, 1) __launch_bounds__(256)
k_sinkhorn() {
    __shared__ __align__(16) float sM[MAXCHUNK * 65];
    __shared__ float su[MAXCHUNK];
    __shared__ float slv[KP];
    __shared__ float wmx[4][KP], wse[4][KP];
    __shared__ float pmx[2][KP], pse[2][KP];

    int t    = blockIdx.x >> 3;
    int rank = blockIdx.x & 7;
    int s = g_start[t];
    int c = g_start[t + 1] - s;
    int chunk = (c + CSIZE - 1) >> 3;
    int r0 = rank * chunk;
    int cn = c - r0;
    if (cn < 0) cn = 0;
    if (cn > chunk) cn = chunk;
    int tid = threadIdx.x, w = tid >> 5, lane = tid & 31;

    for (int idx = tid; idx < cn * KP; idx += 256) {
        int r = idx >> 6, col = idx & 63;
        sM[r * 65 + col] = g_Mp[(s + r0 + r) * KP + col];
    }
    if (tid < KP) slv[tid] = 0.f;
    __syncthreads();

    int q = (cn + 3) >> 2;
    int sub = tid & 3;
    unsigned gmask = 0xFu << (tid & 28);

    for (int it = 0; it < SITERS; it++) {
        // ---- row update: 4 threads per row, 16 cols each
        for (int r = tid >> 2; r < cn; r += 64) {
            const float* row = &sM[r * 65 + sub * 16];
            const float* lv  = &slv[sub * 16];
            float mx = -3.4e38f;
#pragma unroll
            for (int j = 0; j < 16; j++) mx = fmaxf(mx, row[j] + lv[j]);
            mx = fmaxf(mx, __shfl_xor_sync(gmask, mx, 1));
            mx = fmaxf(mx, __shfl_xor_sync(gmask, mx, 2));
            float se = 0.f;
#pragma unroll
            for (int j = 0; j < 16; j++) se += __expf(row[j] + lv[j] - mx);
            se += __shfl_xor_sync(gmask, se, 1);
            se += __shfl_xor_sync(gmask, se, 2);
            if (sub == 0) su[r] = -(mx + __logf(se));
        }
        __syncthreads();

        // ---- column partials: warp w -> cols 32*(w&1)+lane, sub-chunk w>>1
        {
            int col = ((w & 1) << 5) + lane;
            int rs_ = (w >> 1) * q;
            int re_ = min(cn, rs_ + q);
            float mx = -3.4e38f;
            for (int r = rs_; r < re_; r++) mx = fmaxf(mx, sM[r * 65 + col] + su[r]);
            float se = 0.f;
            for (int r = rs_; r < re_; r++) se += __expf(sM[r * 65 + col] + su[r] - mx);
            wmx[w >> 1][col] = mx;
            wse[w >> 1][col] = se;
        }
        __syncthreads();
        int par = it & 1;
        if (tid < KP) {
            float mx = fmaxf(fmaxf(wmx[0][tid], wmx[1][tid]), fmaxf(wmx[2][tid], wmx[3][tid]));
            float se = 0.f;
#pragma unroll
            for (int i = 0; i < 4; i++) se += wse[i][tid] * __expf(wmx[i][tid] - mx);
            pmx[par][tid] = mx;
            pse[par][tid] = se;
        }

        asm volatile("barrier.cluster.arrive.aligned;" ::: "memory");
        asm volatile("barrier.cluster.wait.aligned;" ::: "memory");

        if (tid < KP) {
            unsigned amx = smem_u32(&pmx[par][tid]);
            unsigned ase = smem_u32(&pse[par][tid]);
            float m[CSIZE], sv[CSIZE];
            float MX = -3.4e38f;
#pragma unroll
            for (int rk = 0; rk < CSIZE; rk++) {
                m[rk]  = dsmem_ldf(amx, rk);
                sv[rk] = dsmem_ldf(ase, rk);
                MX = fmaxf(MX, m[rk]);
            }
            float SE = 0.f;
#pragma unroll
            for (int rk = 0; rk < CSIZE; rk++) SE += sv[rk] * __expf(m[rk] - MX);
            slv[tid] = -KLF * (MX + __logf(SE));
        }
        __syncthreads();
    }

    if (tid < cn) g_up[s + r0 + tid] = su[tid];
    if (rank == 0 && tid < KP) g_lv[t * KP + tid] = slv[tid];

    // CRITICAL: no CTA may exit while a peer might still be reading its smem
    // via ld.shared::cluster (final-iteration combine). Cluster-sync before exit.
    asm volatile("barrier.cluster.arrive.aligned;" ::: "memory");
    asm volatile("barrier.cluster.wait.aligned;" ::: "memory");
}

// ---------------- fused output: T (coalesced) + logits --------------------------
__global__ void k_out(const int* __restrict__ jt, float* __restrict__ out) {
    int idx = blockIdx.x * blockDim.x + threadIdx.x;   // over N*NSLOT
    int n = idx / NSLOT;
    int slot = idx - n * NSLOT;
    int k = slot / NT;
    int t = slot - k * NT;
    int tn = jt[n];
    float e = 0.f;
    if (t == tn) {
        int p = g_pos[n];
        e = __expf(g_Mp[p * KP + k] + g_up[p] + g_lv[tn * KP + k]);
        out[n * KP + k] = __logf(e + 1e-8f);
    }
    out[N * KP + idx] = e;
}

__global__ void k_out_logits(const int* __restrict__ jt, float* __restrict__ out) {
    int idx = blockIdx.x * blockDim.x + threadIdx.x;   // over N*KP
    if (idx >= N * KP) return;
    int n = idx >> 6, k = idx & 63;
    int tn = jt[n];
    int p = g_pos[n];
    float e = __expf(g_Mp[p * KP + k] + g_up[p] + g_lv[tn * KP + k]);
    out[n * KP + k] = __logf(e + 1e-8f);
}

// ---------------- launch --------------------------------------------------------
extern "C" void kernel_launch(void* const* d_in, const int* in_sizes, int n_in,
                              void* d_out, int out_size) {
    const float* emb   = (const float*)d_in[0];
    const int*   jt    = (const int*)d_in[1];
    const float* W1    = (const float*)d_in[2];
    const float* b1    = (const float*)d_in[3];
    const float* proto = (const float*)d_in[4];
    float* out = (float*)d_out;
    int write_T = (out_size >= N * KP + N * NSLOT) ? 1 : 0;

    p_hist<<<NBH, 256>>>(jt);
    p_scan<<<1, 256>>>();
    p_scatter<<<NBH, 256>>>(jt);

    k_gemm1<<<dim3(N / 128, H / 128), 256>>>(emb, W1, b1);
    k_gemm2<<<N / 64, 256>>>(proto);

    k_sinkhorn<<<NT * CSIZE, 256>>>();

    if (write_T) k_out<<<(N * NSLOT) / 256, 256>>>(jt, out);
    else         k_out_logits<<<(N * KP) / 256, 256>>>(jt, out);
}

// round 6
// speedup vs baseline: 6.1167x; 1.0697x over previous
#include <cuda_runtime.h>
#include <math.h>

#define N     8192
#define D     256
#define H     512
#define KP    64
#define NT    17
#define NSLOT (KP*NT)       // 1088
#define INV_TAU 20.0f
#define KLF  (1.0f/1.05f)
#define SITERS 50
#define CSIZE 8
#define MAXCHUNK 96
#define NBH   32            // histogram blocks (N/256)

// ---------------- scratch ----------------
__device__ float g_h[N*H];
__device__ float g_Mp[N*KP];      // M = -d2/tau, rows permuted by type
__device__ float g_up[N];
__device__ float g_lv[NT*KP];
__device__ int   g_start[NT+1];
__device__ int   g_perm[N];
__device__ int   g_pos[N];
__device__ int   g_bh[NBH*NT];    // per-block type histograms

// ---------------- packed f32x2 helpers (FFMA2: 2 FMA/lane/issue) ----------------
#define PACK2(dst, lo, hi) asm("mov.b64 %0, {%1, %2};" : "=l"(dst) : "f"(lo), "f"(hi))
#define BCAST2(dst, x)     asm("mov.b64 %0, {%1, %1};" : "=l"(dst) : "f"(x))
#define FFMA2(c, a, b)     asm("fma.rn.f32x2 %0, %1, %2, %0;" : "+l"(c) : "l"(a), "l"(b))
#define UNPACK2(lo, hi, s) asm("mov.b64 {%0, %1}, %2;" : "=f"(lo), "=f"(hi) : "l"(s))

__device__ __forceinline__ unsigned smem_u32(const void* p) {
    unsigned a;
    asm("{ .reg .u64 t; cvta.to.shared.u64 t, %1; cvt.u32.u64 %0, t; }" : "=r"(a) : "l"(p));
    return a;
}
__device__ __forceinline__ float dsmem_ldf(unsigned laddr, unsigned rank) {
    unsigned r; float v;
    asm volatile("mapa.shared::cluster.u32 %0, %1, %2;" : "=r"(r) : "r"(laddr), "r"(rank));
    asm volatile("ld.shared::cluster.f32 %0, [%1];" : "=f"(v) : "r"(r));
    return v;
}

// ---------------- parallel stable counting sort (2 kernels) ---------------------
__global__ void p_hist(const int* __restrict__ jt) {
    __shared__ int h[8][NT];
    int tid = threadIdx.x, w = tid >> 5, lane = tid & 31, b = blockIdx.x;
    if (tid < 8 * NT) ((int*)h)[tid] = 0;
    __syncthreads();
    int t = jt[b * 256 + tid];
    unsigned mask = __match_any_sync(0xffffffffu, t);
    int rnk = __popc(mask & ((1u << lane) - 1u));
    if (rnk == 0) h[w][t] = __popc(mask);
    __syncthreads();
    if (tid < NT) {
        int s = 0;
#pragma unroll
        for (int ww = 0; ww < 8; ww++) s += h[ww][tid];
        g_bh[b * NT + tid] = s;
    }
}

// scatter with inlined global scan (every block redoes the tiny 17x32 scan)
__global__ void p_scatter(const int* __restrict__ jt) {
    __shared__ int cnt[NT];
    __shared__ int sstart[NT];
    __shared__ int soff[NT];
    __shared__ int h[8][NT];
    __shared__ int off[8][NT];
    int tid = threadIdx.x, w = tid >> 5, lane = tid & 31, b = blockIdx.x;
    if (tid < 8 * NT) ((int*)h)[tid] = 0;
    if (tid < NT) {
        int s = 0;
        for (int bb = 0; bb < NBH; bb++) s += g_bh[bb * NT + tid];
        cnt[tid] = s;
    }
    __syncthreads();
    if (tid == 0) {
        int s = 0;
        for (int t = 0; t < NT; t++) { sstart[t] = s; s += cnt[t]; }
        if (b == 0) {
            for (int t = 0; t < NT; t++) g_start[t] = sstart[t];
            g_start[NT] = s;
        }
    }
    __syncthreads();
    if (tid < NT) {
        int run = sstart[tid];
        for (int bb = 0; bb < b; bb++) run += g_bh[bb * NT + tid];
        soff[tid] = run;
    }
    int n = b * 256 + tid;
    int t = jt[n];
    unsigned mask = __match_any_sync(0xffffffffu, t);
    int rnk = __popc(mask & ((1u << lane) - 1u));
    if (rnk == 0) h[w][t] = __popc(mask);
    __syncthreads();
    if (tid < NT) {
        int run = soff[tid];
#pragma unroll
        for (int ww = 0; ww < 8; ww++) { off[ww][tid] = run; run += h[ww][tid]; }
    }
    __syncthreads();
    int pos = off[w][t] + rnk;
    g_perm[pos] = n;
    g_pos[n]  = pos;
}

// ---------------- GEMM1: h = selu(emb @ W1 + b1), f32x2 packed ------------------
// 256x128 tile, BK=16, 512 threads, 8x8 microtile (4 row-pair x 8 col packed)
// static shared: 16*260 + 16*128 + 128 floats = 25.3 KB (< 48 KB, no attribute)
__global__ void __launch_bounds__(512) k_gemm1(const float* __restrict__ A,
                                               const float* __restrict__ W,
                                               const float* __restrict__ bias) {
    __shared__ __align__(16) float As[16][260];   // k-major
    __shared__ __align__(16) float Bs[16][128];
    __shared__ float sb[128];
    int bm = blockIdx.x * 256, bn = blockIdx.y * 128;
    int tid = threadIdx.x;
    int ty = tid >> 4, tx = tid & 15;   // 32 x 16
    if (tid < 128) sb[tid] = bias[bn + tid];

    unsigned long long acc[4][8];
#pragma unroll
    for (int i = 0; i < 4; i++)
#pragma unroll
        for (int j = 0; j < 8; j++) acc[i][j] = 0ULL;

    for (int k0 = 0; k0 < D; k0 += 16) {
#pragma unroll
        for (int i = 0; i < 2; i++) {              // A: 256x16 = 1024 float4
            int idx = tid + i * 512;
            int r = idx >> 2, c4 = idx & 3;
            float4 v = *(const float4*)&A[(bm + r) * D + k0 + c4 * 4];
            As[c4 * 4 + 0][r] = v.x;
            As[c4 * 4 + 1][r] = v.y;
            As[c4 * 4 + 2][r] = v.z;
            As[c4 * 4 + 3][r] = v.w;
        }
        {                                          // B: 16x128 = 512 float4
            int k = tid >> 5, n4 = tid & 31;
            *(float4*)&Bs[k][n4 * 4] = *(const float4*)&W[(k0 + k) * H + bn + n4 * 4];
        }
        __syncthreads();
#pragma unroll
        for (int kk = 0; kk < 16; kk++) {
            float4 a0 = *(const float4*)&As[kk][ty * 8];
            float4 a1 = *(const float4*)&As[kk][ty * 8 + 4];
            float4 b0 = *(const float4*)&Bs[kk][tx * 8];
            float4 b1 = *(const float4*)&Bs[kk][tx * 8 + 4];
            unsigned long long ap[4], bb[8];
            PACK2(ap[0], a0.x, a0.y); PACK2(ap[1], a0.z, a0.w);
            PACK2(ap[2], a1.x, a1.y); PACK2(ap[3], a1.z, a1.w);
            float bf[8] = {b0.x, b0.y, b0.z, b0.w, b1.x, b1.y, b1.z, b1.w};
#pragma unroll
            for (int j = 0; j < 8; j++) BCAST2(bb[j], bf[j]);
#pragma unroll
            for (int pi = 0; pi < 4; pi++)
#pragma unroll
                for (int j = 0; j < 8; j++) FFMA2(acc[pi][j], ap[pi], bb[j]);
        }
        __syncthreads();
    }
    const float SC = 1.0507009873554805f;
    const float AL = 1.6732632423543772f;
#pragma unroll
    for (int pi = 0; pi < 4; pi++) {
        float o0[8], o1[8];
#pragma unroll
        for (int j = 0; j < 8; j++) {
            float x0, x1;
            UNPACK2(x0, x1, acc[pi][j]);
            x0 += sb[tx * 8 + j];
            x1 += sb[tx * 8 + j];
            o0[j] = (x0 > 0.f) ? SC * x0 : SC * AL * expm1f(x0);
            o1[j] = (x1 > 0.f) ? SC * x1 : SC * AL * expm1f(x1);
        }
        int row0 = bm + ty * 8 + pi * 2;
        *(float4*)&g_h[row0 * H + bn + tx * 8]           = make_float4(o0[0], o0[1], o0[2], o0[3]);
        *(float4*)&g_h[row0 * H + bn + tx * 8 + 4]       = make_float4(o0[4], o0[5], o0[6], o0[7]);
        *(float4*)&g_h[(row0 + 1) * H + bn + tx * 8]     = make_float4(o1[0], o1[1], o1[2], o1[3]);
        *(float4*)&g_h[(row0 + 1) * H + bn + tx * 8 + 4] = make_float4(o1[4], o1[5], o1[6], o1[7]);
    }
}

// ---------------- GEMM2: d2 -> M, f32x2 packed, fused norms ---------------------
// BM=64, BN=64, BK=32, 256 threads (16x16), 4x4 microtile (2 row-pair x 4)
__global__ void __launch_bounds__(256) k_gemm2(const float* __restrict__ proto) {
    __shared__ __align__(16) float Hs[32][68];
    __shared__ __align__(16) float Ps[32][68];
    __shared__ float shn[64];
    __shared__ float spn[64];
    int bm = blockIdx.x * 64;
    int tid = threadIdx.x;
    int ty = tid >> 4, tx = tid & 15;
    int lr = tid >> 3, lc = tid & 7;

    unsigned long long acc[2][4];
#pragma unroll
    for (int i = 0; i < 2; i++)
#pragma unroll
        for (int j = 0; j < 4; j++) acc[i][j] = 0ULL;
    float hn0 = 0.f, hn1 = 0.f, pn0 = 0.f, pn1 = 0.f;

    for (int j0 = 0; j0 < H; j0 += 32) {
        {
            float4 v = *(const float4*)&g_h[(bm + lr) * H + j0 + lc * 4];
            Hs[lc * 4 + 0][lr] = v.x; Hs[lc * 4 + 1][lr] = v.y;
            Hs[lc * 4 + 2][lr] = v.z; Hs[lc * 4 + 3][lr] = v.w;
            hn0 += v.x * v.x + v.y * v.y + v.z * v.z + v.w * v.w;
            float4 u = *(const float4*)&g_h[(bm + lr + 32) * H + j0 + lc * 4];
            Hs[lc * 4 + 0][lr + 32] = u.x; Hs[lc * 4 + 1][lr + 32] = u.y;
            Hs[lc * 4 + 2][lr + 32] = u.z; Hs[lc * 4 + 3][lr + 32] = u.w;
            hn1 += u.x * u.x + u.y * u.y + u.z * u.z + u.w * u.w;
        }
        {
            float4 v = *(const float4*)&proto[lr * H + j0 + lc * 4];
            Ps[lc * 4 + 0][lr] = v.x; Ps[lc * 4 + 1][lr] = v.y;
            Ps[lc * 4 + 2][lr] = v.z; Ps[lc * 4 + 3][lr] = v.w;
            pn0 += v.x * v.x + v.y * v.y + v.z * v.z + v.w * v.w;
            float4 u = *(const float4*)&proto[(lr + 32) * H + j0 + lc * 4];
            Ps[lc * 4 + 0][lr + 32] = u.x; Ps[lc * 4 + 1][lr + 32] = u.y;
            Ps[lc * 4 + 2][lr + 32] = u.z; Ps[lc * 4 + 3][lr + 32] = u.w;
            pn1 += u.x * u.x + u.y * u.y + u.z * u.z + u.w * u.w;
        }
        __syncthreads();
#pragma unroll
        for (int kk = 0; kk < 32; kk++) {
            float4 a = *(const float4*)&Hs[kk][ty * 4];
            float4 b = *(const float4*)&Ps[kk][tx * 4];
            unsigned long long ap[2], bb[4];
            PACK2(ap[0], a.x, a.y); PACK2(ap[1], a.z, a.w);
            BCAST2(bb[0], b.x); BCAST2(bb[1], b.y);
            BCAST2(bb[2], b.z); BCAST2(bb[3], b.w);
#pragma unroll
            for (int pi = 0; pi < 2; pi++)
#pragma unroll
                for (int j = 0; j < 4; j++) FFMA2(acc[pi][j], ap[pi], bb[j]);
        }
        __syncthreads();
    }
#pragma unroll
    for (int o = 1; o < 8; o <<= 1) {
        hn0 += __shfl_xor_sync(0xffffffffu, hn0, o);
        hn1 += __shfl_xor_sync(0xffffffffu, hn1, o);
        pn0 += __shfl_xor_sync(0xffffffffu, pn0, o);
        pn1 += __shfl_xor_sync(0xffffffffu, pn1, o);
    }
    if (lc == 0) { shn[lr] = hn0; shn[lr + 32] = hn1; spn[lr] = pn0; spn[lr + 32] = pn1; }
    __syncthreads();

#pragma unroll
    for (int pi = 0; pi < 2; pi++) {
        float c0[4], c1[4];
#pragma unroll
        for (int j = 0; j < 4; j++) UNPACK2(c0[j], c1[j], acc[pi][j]);
        int n0 = bm + ty * 4 + pi * 2;
        float hnA = shn[ty * 4 + pi * 2], hnB = shn[ty * 4 + pi * 2 + 1];
        int pA = g_pos[n0], pB = g_pos[n0 + 1];
        float oA[4], oB[4];
#pragma unroll
        for (int j = 0; j < 4; j++) {
            float pn = spn[tx * 4 + j];
            oA[j] = -INV_TAU * fmaxf(hnA + pn - 2.f * c0[j], 0.f);
            oB[j] = -INV_TAU * fmaxf(hnB + pn - 2.f * c1[j], 0.f);
        }
        *(float4*)&g_Mp[pA * KP + tx * 4] = make_float4(oA[0], oA[1], oA[2], oA[3]);
        *(float4*)&g_Mp[pB * KP + tx * 4] = make_float4(oB[0], oB[1], oB[2], oB[3]);
    }
}

// ---------------- Sinkhorn: 17 types x 8-CTA clusters ---------------------------
__global__ void __cluster_dims__(CSIZE, 1, 1) __launch_bounds__(256)
k_sinkhorn() {
    __shared__ __align__(16) float sM[MAXCHUNK * 65];
    __shared__ float su[MAXCHUNK];
    __shared__ float slv[KP];
    __shared__ float wmx[4][KP], wse[4][KP];
    __shared__ float pmx[2][KP], pse[2][KP];

    int t    = blockIdx.x >> 3;
    int rank = blockIdx.x & 7;
    int s = g_start[t];
    int c = g_start[t + 1] - s;
    int chunk = (c + CSIZE - 1) >> 3;
    int r0 = rank * chunk;
    int cn = c - r0;
    if (cn < 0) cn = 0;
    if (cn > chunk) cn = chunk;
    int tid = threadIdx.x, w = tid >> 5, lane = tid & 31;

    for (int idx = tid; idx < cn * KP; idx += 256) {
        int r = idx >> 6, col = idx & 63;
        sM[r * 65 + col] = g_Mp[(s + r0 + r) * KP + col];
    }
    if (tid < KP) slv[tid] = 0.f;
    __syncthreads();

    int q = (cn + 3) >> 2;
    int sub = tid & 3;
    unsigned gmask = 0xFu << (tid & 28);
    int col = ((w & 1) << 5) + lane;
    int rs_ = (w >> 1) * q;
    int re_ = min(cn, rs_ + q);
    int nr  = re_ - rs_;

    for (int it = 0; it < SITERS; it++) {
        // ---- row update: 4 threads/row, lv cached in registers, single pass
        float lvr[16];
#pragma unroll
        for (int j = 0; j < 16; j++) lvr[j] = slv[sub * 16 + j];
        for (int r = tid >> 2; r < cn; r += 64) {
            const float* row = &sM[r * 65 + sub * 16];
            float v[16];
            float mx = -3.4e38f;
#pragma unroll
            for (int j = 0; j < 16; j++) { v[j] = row[j] + lvr[j]; mx = fmaxf(mx, v[j]); }
            mx = fmaxf(mx, __shfl_xor_sync(gmask, mx, 1));
            mx = fmaxf(mx, __shfl_xor_sync(gmask, mx, 2));
            float se = 0.f;
#pragma unroll
            for (int j = 0; j < 16; j++) se += __expf(v[j] - mx);
            se += __shfl_xor_sync(gmask, se, 1);
            se += __shfl_xor_sync(gmask, se, 2);
            if (sub == 0) su[r] = -(mx + __logf(se));
        }
        __syncthreads();

        // ---- column partials: value-cached single pass
        {
            float v[24];
            float mx = -3.4e38f;
#pragma unroll
            for (int i = 0; i < 24; i++) {
                if (i >= nr) break;
                v[i] = sM[(rs_ + i) * 65 + col] + su[rs_ + i];
                mx = fmaxf(mx, v[i]);
            }
            float se = 0.f;
#pragma unroll
            for (int i = 0; i < 24; i++) {
                if (i >= nr) break;
                se += __expf(v[i] - mx);
            }
            wmx[w >> 1][col] = mx;
            wse[w >> 1][col] = se;
        }
        __syncthreads();
        int par = it & 1;
        if (tid < KP) {
            float mx = fmaxf(fmaxf(wmx[0][tid], wmx[1][tid]), fmaxf(wmx[2][tid], wmx[3][tid]));
            float se = 0.f;
#pragma unroll
            for (int i = 0; i < 4; i++) se += wse[i][tid] * __expf(wmx[i][tid] - mx);
            pmx[par][tid] = mx;
            pse[par][tid] = se;
        }

        asm volatile("barrier.cluster.arrive.aligned;" ::: "memory");
        asm volatile("barrier.cluster.wait.aligned;" ::: "memory");

        if (tid < KP) {
            unsigned amx = smem_u32(&pmx[par][tid]);
            unsigned ase = smem_u32(&pse[par][tid]);
            float m[CSIZE], sv[CSIZE];
            float MX = -3.4e38f;
#pragma unroll
            for (int rk = 0; rk < CSIZE; rk++) {
                m[rk]  = dsmem_ldf(amx, rk);
                sv[rk] = dsmem_ldf(ase, rk);
                MX = fmaxf(MX, m[rk]);
            }
            float SE = 0.f;
#pragma unroll
            for (int rk = 0; rk < CSIZE; rk++) SE += sv[rk] * __expf(m[rk] - MX);
            slv[tid] = -KLF * (MX + __logf(SE));
        }
        __syncthreads();
    }

    if (tid < cn) g_up[s + r0 + tid] = su[tid];
    if (rank == 0 && tid < KP) g_lv[t * KP + tid] = slv[tid];

    // no CTA may exit while a peer might still read its smem (final combine)
    asm volatile("barrier.cluster.arrive.aligned;" ::: "memory");
    asm volatile("barrier.cluster.wait.aligned;" ::: "memory");
}

// ---------------- fused output: T (float4 coalesced) + logits -------------------
__global__ void k_out(const int* __restrict__ jt, float* __restrict__ out) {
    int idx4 = blockIdx.x * blockDim.x + threadIdx.x;   // over N*NSLOT/4
    int base = idx4 * 4;
    int n = base / NSLOT;
    int s0 = base - n * NSLOT;
    int tn = jt[n];
    int p = g_pos[n];
    float up = g_up[p];
    float e[4] = {0.f, 0.f, 0.f, 0.f};
#pragma unroll
    for (int q = 0; q < 4; q++) {
        int slot = s0 + q;
        int k = slot / NT;
        int t = slot - k * NT;
        if (t == tn) {
            float ev = __expf(g_Mp[p * KP + k] + up + g_lv[tn * KP + k]);
            e[q] = ev;
            out[n * KP + k] = __logf(ev + 1e-8f);
        }
    }
    *(float4*)&out[N * KP + base] = make_float4(e[0], e[1], e[2], e[3]);
}

__global__ void k_out_logits(const int* __restrict__ jt, float* __restrict__ out) {
    int idx = blockIdx.x * blockDim.x + threadIdx.x;   // over N*KP
    if (idx >= N * KP) return;
    int n = idx >> 6, k = idx & 63;
    int tn = jt[n];
    int p = g_pos[n];
    float e = __expf(g_Mp[p * KP + k] + g_up[p] + g_lv[tn * KP + k]);
    out[n * KP + k] = __logf(e + 1e-8f);
}

// ---------------- launch --------------------------------------------------------
extern "C" void kernel_launch(void* const* d_in, const int* in_sizes, int n_in,
                              void* d_out, int out_size) {
    const float* emb   = (const float*)d_in[0];
    const int*   jt    = (const int*)d_in[1];
    const float* W1    = (const float*)d_in[2];
    const float* b1    = (const float*)d_in[3];
    const float* proto = (const float*)d_in[4];
    float* out = (float*)d_out;
    int write_T = (out_size >= N * KP + N * NSLOT) ? 1 : 0;

    p_hist<<<NBH, 256>>>(jt);
    p_scatter<<<NBH, 256>>>(jt);

    k_gemm1<<<dim3(N / 256, H / 128), 512>>>(emb, W1, b1);
    k_gemm2<<<N / 64, 256>>>(proto);

    k_sinkhorn<<<NT * CSIZE, 256>>>();

    if (write_T) k_out<<<(N * NSLOT / 4) / 256, 256>>>(jt, out);
    else         k_out_logits<<<(N * KP) / 256, 256>>>(jt, out);
}

// round 7
// speedup vs baseline: 6.3659x; 1.0407x over previous
#include <cuda_runtime.h>
#include <math.h>

#define N     8192
#define D     256
#define H     512
#define KP    64
#define NT    17
#define NSLOT (KP*NT)       // 1088
#define INV_TAU 20.0f
#define KLF  (1.0f/1.05f)
#define SITERS 50
#define CSIZE 8
#define MAXCHUNK 96
#define NBH   32            // histogram blocks (N/256)

// ---------------- scratch ----------------
__device__ float g_h[N*H];
__device__ float g_Mp[N*KP];      // M = -d2/tau, rows permuted by type
__device__ float g_up[N];
__device__ float g_lv[NT*KP];
__device__ int   g_start[NT+1];
__device__ int   g_perm[N];
__device__ int   g_pos[N];
__device__ int   g_bh[NBH*NT];    // per-block type histograms

// ---------------- packed f32x2 helpers (FFMA2: 2 FMA/lane/issue) ----------------
#define PACK2(dst, lo, hi) asm("mov.b64 %0, {%1, %2};" : "=l"(dst) : "f"(lo), "f"(hi))
#define BCAST2(dst, x)     asm("mov.b64 %0, {%1, %1};" : "=l"(dst) : "f"(x))
#define FFMA2(c, a, b)     asm("fma.rn.f32x2 %0, %1, %2, %0;" : "+l"(c) : "l"(a), "l"(b))
#define UNPACK2(lo, hi, s) asm("mov.b64 {%0, %1}, %2;" : "=f"(lo), "=f"(hi) : "l"(s))

__device__ __forceinline__ unsigned smem_u32(const void* p) {
    unsigned a;
    asm("{ .reg .u64 t; cvta.to.shared.u64 t, %1; cvt.u32.u64 %0, t; }" : "=r"(a) : "l"(p));
    return a;
}
__device__ __forceinline__ float dsmem_ldf(unsigned laddr, unsigned rank) {
    unsigned r; float v;
    asm volatile("mapa.shared::cluster.u32 %0, %1, %2;" : "=r"(r) : "r"(laddr), "r"(rank));
    asm volatile("ld.shared::cluster.f32 %0, [%1];" : "=f"(v) : "r"(r));
    return v;
}

// ---------------- parallel stable counting sort (2 kernels) ---------------------
__global__ void p_hist(const int* __restrict__ jt) {
    __shared__ int h[8][NT];
    int tid = threadIdx.x, w = tid >> 5, lane = tid & 31, b = blockIdx.x;
    if (tid < 8 * NT) ((int*)h)[tid] = 0;
    __syncthreads();
    int t = jt[b * 256 + tid];
    unsigned mask = __match_any_sync(0xffffffffu, t);
    int rnk = __popc(mask & ((1u << lane) - 1u));
    if (rnk == 0) h[w][t] = __popc(mask);
    __syncthreads();
    if (tid < NT) {
        int s = 0;
#pragma unroll
        for (int ww = 0; ww < 8; ww++) s += h[ww][tid];
        g_bh[b * NT + tid] = s;
    }
}

__global__ void p_scatter(const int* __restrict__ jt) {
    __shared__ int cnt[NT];
    __shared__ int sstart[NT];
    __shared__ int soff[NT];
    __shared__ int h[8][NT];
    __shared__ int off[8][NT];
    int tid = threadIdx.x, w = tid >> 5, lane = tid & 31, b = blockIdx.x;
    if (tid < 8 * NT) ((int*)h)[tid] = 0;
    if (tid < NT) {
        int s = 0;
        for (int bb = 0; bb < NBH; bb++) s += g_bh[bb * NT + tid];
        cnt[tid] = s;
    }
    __syncthreads();
    if (tid == 0) {
        int s = 0;
        for (int t = 0; t < NT; t++) { sstart[t] = s; s += cnt[t]; }
        if (b == 0) {
            for (int t = 0; t < NT; t++) g_start[t] = sstart[t];
            g_start[NT] = s;
        }
    }
    __syncthreads();
    if (tid < NT) {
        int run = sstart[tid];
        for (int bb = 0; bb < b; bb++) run += g_bh[bb * NT + tid];
        soff[tid] = run;
    }
    int n = b * 256 + tid;
    int t = jt[n];
    unsigned mask = __match_any_sync(0xffffffffu, t);
    int rnk = __popc(mask & ((1u << lane) - 1u));
    if (rnk == 0) h[w][t] = __popc(mask);
    __syncthreads();
    if (tid < NT) {
        int run = soff[tid];
#pragma unroll
        for (int ww = 0; ww < 8; ww++) { off[ww][tid] = run; run += h[ww][tid]; }
    }
    __syncthreads();
    int pos = off[w][t] + rnk;
    g_perm[pos] = n;
    g_pos[n]  = pos;
}

// ---------------- GEMM1: h = selu(emb @ W1 + b1), f32x2 + sw pipeline -----------
// 256x128 tile, BK=16, 512 threads, 8x8 microtile (4 row-pair x 8 col packed)
__global__ void __launch_bounds__(512) k_gemm1(const float* __restrict__ A,
                                               const float* __restrict__ W,
                                               const float* __restrict__ bias) {
    __shared__ __align__(16) float As[16][260];   // k-major
    __shared__ __align__(16) float Bs[16][128];
    __shared__ float sb[128];
    int bm = blockIdx.x * 256, bn = blockIdx.y * 128;
    int tid = threadIdx.x;
    int ty = tid >> 4, tx = tid & 15;   // 32 x 16
    if (tid < 128) sb[tid] = bias[bn + tid];

    // loader indices
    int ar0 = tid >> 2,        ac4_0 = tid & 3;          // A part 0
    int ar1 = (tid + 512) >> 2, ac4_1 = tid & 3;         // A part 1
    int bk  = tid >> 5,        bn4  = tid & 31;          // B

    unsigned long long acc[4][8];
#pragma unroll
    for (int i = 0; i < 4; i++)
#pragma unroll
        for (int j = 0; j < 8; j++) acc[i][j] = 0ULL;

    // prologue: stage first tile
    float4 pa0 = *(const float4*)&A[(bm + ar0) * D + ac4_0 * 4];
    float4 pa1 = *(const float4*)&A[(bm + ar1) * D + ac4_1 * 4];
    float4 pbv = *(const float4*)&W[bk * H + bn + bn4 * 4];

    for (int k0 = 0; k0 < D; k0 += 16) {
        // commit staged tile to smem
        As[ac4_0 * 4 + 0][ar0] = pa0.x; As[ac4_0 * 4 + 1][ar0] = pa0.y;
        As[ac4_0 * 4 + 2][ar0] = pa0.z; As[ac4_0 * 4 + 3][ar0] = pa0.w;
        As[ac4_1 * 4 + 0][ar1] = pa1.x; As[ac4_1 * 4 + 1][ar1] = pa1.y;
        As[ac4_1 * 4 + 2][ar1] = pa1.z; As[ac4_1 * 4 + 3][ar1] = pa1.w;
        *(float4*)&Bs[bk][bn4 * 4] = pbv;
        __syncthreads();

        // prefetch next tile (overlaps with compute below)
        if (k0 + 16 < D) {
            pa0 = *(const float4*)&A[(bm + ar0) * D + k0 + 16 + ac4_0 * 4];
            pa1 = *(const float4*)&A[(bm + ar1) * D + k0 + 16 + ac4_1 * 4];
            pbv = *(const float4*)&W[(k0 + 16 + bk) * H + bn + bn4 * 4];
        }

#pragma unroll
        for (int kk = 0; kk < 16; kk++) {
            float4 a0 = *(const float4*)&As[kk][ty * 8];
            float4 a1 = *(const float4*)&As[kk][ty * 8 + 4];
            float4 b0 = *(const float4*)&Bs[kk][tx * 8];
            float4 b1 = *(const float4*)&Bs[kk][tx * 8 + 4];
            unsigned long long ap[4], bb[8];
            PACK2(ap[0], a0.x, a0.y); PACK2(ap[1], a0.z, a0.w);
            PACK2(ap[2], a1.x, a1.y); PACK2(ap[3], a1.z, a1.w);
            float bf[8] = {b0.x, b0.y, b0.z, b0.w, b1.x, b1.y, b1.z, b1.w};
#pragma unroll
            for (int j = 0; j < 8; j++) BCAST2(bb[j], bf[j]);
#pragma unroll
            for (int pi = 0; pi < 4; pi++)
#pragma unroll
                for (int j = 0; j < 8; j++) FFMA2(acc[pi][j], ap[pi], bb[j]);
        }
        __syncthreads();
    }
    const float SC = 1.0507009873554805f;
    const float AL = 1.6732632423543772f;
#pragma unroll
    for (int pi = 0; pi < 4; pi++) {
        float o0[8], o1[8];
#pragma unroll
        for (int j = 0; j < 8; j++) {
            float x0, x1;
            UNPACK2(x0, x1, acc[pi][j]);
            x0 += sb[tx * 8 + j];
            x1 += sb[tx * 8 + j];
            o0[j] = (x0 > 0.f) ? SC * x0 : SC * AL * expm1f(x0);
            o1[j] = (x1 > 0.f) ? SC * x1 : SC * AL * expm1f(x1);
        }
        int row0 = bm + ty * 8 + pi * 2;
        *(float4*)&g_h[row0 * H + bn + tx * 8]           = make_float4(o0[0], o0[1], o0[2], o0[3]);
        *(float4*)&g_h[row0 * H + bn + tx * 8 + 4]       = make_float4(o0[4], o0[5], o0[6], o0[7]);
        *(float4*)&g_h[(row0 + 1) * H + bn + tx * 8]     = make_float4(o1[0], o1[1], o1[2], o1[3]);
        *(float4*)&g_h[(row0 + 1) * H + bn + tx * 8 + 4] = make_float4(o1[4], o1[5], o1[6], o1[7]);
    }
}

// ---------------- GEMM2: d2 -> M, f32x2 + sw pipeline, fused norms --------------
// BM=64, BN=64, BK=32, 256 threads (16x16), 2 row-pair x 4 packed microtile
__global__ void __launch_bounds__(256) k_gemm2(const float* __restrict__ proto) {
    __shared__ __align__(16) float Hs[32][68];
    __shared__ __align__(16) float Ps[32][68];
    __shared__ float shn[64];
    __shared__ float spn[64];
    int bm = blockIdx.x * 64;
    int tid = threadIdx.x;
    int ty = tid >> 4, tx = tid & 15;
    int lr = tid >> 3, lc = tid & 7;

    unsigned long long acc[2][4];
#pragma unroll
    for (int i = 0; i < 2; i++)
#pragma unroll
        for (int j = 0; j < 4; j++) acc[i][j] = 0ULL;
    float hn0 = 0.f, hn1 = 0.f, pn0 = 0.f, pn1 = 0.f;

    // prologue: stage first tile
    float4 sh0 = *(const float4*)&g_h[(bm + lr) * H + lc * 4];
    float4 sh1 = *(const float4*)&g_h[(bm + lr + 32) * H + lc * 4];
    float4 sp0 = *(const float4*)&proto[lr * H + lc * 4];
    float4 sp1 = *(const float4*)&proto[(lr + 32) * H + lc * 4];

    for (int j0 = 0; j0 < H; j0 += 32) {
        // commit staged tile + accumulate norms
        Hs[lc * 4 + 0][lr] = sh0.x; Hs[lc * 4 + 1][lr] = sh0.y;
        Hs[lc * 4 + 2][lr] = sh0.z; Hs[lc * 4 + 3][lr] = sh0.w;
        hn0 += sh0.x * sh0.x + sh0.y * sh0.y + sh0.z * sh0.z + sh0.w * sh0.w;
        Hs[lc * 4 + 0][lr + 32] = sh1.x; Hs[lc * 4 + 1][lr + 32] = sh1.y;
        Hs[lc * 4 + 2][lr + 32] = sh1.z; Hs[lc * 4 + 3][lr + 32] = sh1.w;
        hn1 += sh1.x * sh1.x + sh1.y * sh1.y + sh1.z * sh1.z + sh1.w * sh1.w;
        Ps[lc * 4 + 0][lr] = sp0.x; Ps[lc * 4 + 1][lr] = sp0.y;
        Ps[lc * 4 + 2][lr] = sp0.z; Ps[lc * 4 + 3][lr] = sp0.w;
        pn0 += sp0.x * sp0.x + sp0.y * sp0.y + sp0.z * sp0.z + sp0.w * sp0.w;
        Ps[lc * 4 + 0][lr + 32] = sp1.x; Ps[lc * 4 + 1][lr + 32] = sp1.y;
        Ps[lc * 4 + 2][lr + 32] = sp1.z; Ps[lc * 4 + 3][lr + 32] = sp1.w;
        pn1 += sp1.x * sp1.x + sp1.y * sp1.y + sp1.z * sp1.z + sp1.w * sp1.w;
        __syncthreads();

        // prefetch next tile
        if (j0 + 32 < H) {
            sh0 = *(const float4*)&g_h[(bm + lr) * H + j0 + 32 + lc * 4];
            sh1 = *(const float4*)&g_h[(bm + lr + 32) * H + j0 + 32 + lc * 4];
            sp0 = *(const float4*)&proto[lr * H + j0 + 32 + lc * 4];
            sp1 = *(const float4*)&proto[(lr + 32) * H + j0 + 32 + lc * 4];
        }

#pragma unroll
        for (int kk = 0; kk < 32; kk++) {
            float4 a = *(const float4*)&Hs[kk][ty * 4];
            float4 b = *(const float4*)&Ps[kk][tx * 4];
            unsigned long long ap[2], bb[4];
            PACK2(ap[0], a.x, a.y); PACK2(ap[1], a.z, a.w);
            BCAST2(bb[0], b.x); BCAST2(bb[1], b.y);
            BCAST2(bb[2], b.z); BCAST2(bb[3], b.w);
#pragma unroll
            for (int pi = 0; pi < 2; pi++)
#pragma unroll
                for (int j = 0; j < 4; j++) FFMA2(acc[pi][j], ap[pi], bb[j]);
        }
        __syncthreads();
    }
#pragma unroll
    for (int o = 1; o < 8; o <<= 1) {
        hn0 += __shfl_xor_sync(0xffffffffu, hn0, o);
        hn1 += __shfl_xor_sync(0xffffffffu, hn1, o);
        pn0 += __shfl_xor_sync(0xffffffffu, pn0, o);
        pn1 += __shfl_xor_sync(0xffffffffu, pn1, o);
    }
    if (lc == 0) { shn[lr] = hn0; shn[lr + 32] = hn1; spn[lr] = pn0; spn[lr + 32] = pn1; }
    __syncthreads();

#pragma unroll
    for (int pi = 0; pi < 2; pi++) {
        float c0[4], c1[4];
#pragma unroll
        for (int j = 0; j < 4; j++) UNPACK2(c0[j], c1[j], acc[pi][j]);
        int n0 = bm + ty * 4 + pi * 2;
        float hnA = shn[ty * 4 + pi * 2], hnB = shn[ty * 4 + pi * 2 + 1];
        int pA = g_pos[n0], pB = g_pos[n0 + 1];
        float oA[4], oB[4];
#pragma unroll
        for (int j = 0; j < 4; j++) {
            float pn = spn[tx * 4 + j];
            oA[j] = -INV_TAU * fmaxf(hnA + pn - 2.f * c0[j], 0.f);
            oB[j] = -INV_TAU * fmaxf(hnB + pn - 2.f * c1[j], 0.f);
        }
        *(float4*)&g_Mp[pA * KP + tx * 4] = make_float4(oA[0], oA[1], oA[2], oA[3]);
        *(float4*)&g_Mp[pB * KP + tx * 4] = make_float4(oB[0], oB[1], oB[2], oB[3]);
    }
}

// ---------------- Sinkhorn: 17 types x 8-CTA clusters ---------------------------
__global__ void __cluster_dims__(CSIZE, 1, 1) __launch_bounds__(256)
k_sinkhorn() {
    __shared__ __align__(16) float sM[MAXCHUNK * 65];
    __shared__ float su[MAXCHUNK];
    __shared__ float slv[KP];
    __shared__ float wmx[4][KP], wse[4][KP];
    __shared__ float pmx[2][KP], pse[2][KP];

    int t    = blockIdx.x >> 3;
    int rank = blockIdx.x & 7;
    int s = g_start[t];
    int c = g_start[t + 1] - s;
    int chunk = (c + CSIZE - 1) >> 3;
    int r0 = rank * chunk;
    int cn = c - r0;
    if (cn < 0) cn = 0;
    if (cn > chunk) cn = chunk;
    int tid = threadIdx.x, w = tid >> 5, lane = tid & 31;

    for (int idx = tid; idx < cn * KP; idx += 256) {
        int r = idx >> 6, col = idx & 63;
        sM[r * 65 + col] = g_Mp[(s + r0 + r) * KP + col];
    }
    if (tid < KP) slv[tid] = 0.f;
    __syncthreads();

    int q = (cn + 3) >> 2;
    int sub = tid & 3;
    unsigned gmask = 0xFu << (tid & 28);
    int col = ((w & 1) << 5) + lane;
    int rs_ = (w >> 1) * q;
    int re_ = min(cn, rs_ + q);
    int nr  = re_ - rs_;

    for (int it = 0; it < SITERS; it++) {
        // ---- row update: 4 threads/row, lv cached in registers, single pass
        float lvr[16];
#pragma unroll
        for (int j = 0; j < 16; j++) lvr[j] = slv[sub * 16 + j];
        for (int r = tid >> 2; r < cn; r += 64) {
            const float* row = &sM[r * 65 + sub * 16];
            float v[16];
            float mx = -3.4e38f;
#pragma unroll
            for (int j = 0; j < 16; j++) { v[j] = row[j] + lvr[j]; mx = fmaxf(mx, v[j]); }
            mx = fmaxf(mx, __shfl_xor_sync(gmask, mx, 1));
            mx = fmaxf(mx, __shfl_xor_sync(gmask, mx, 2));
            float se = 0.f;
#pragma unroll
            for (int j = 0; j < 16; j++) se += __expf(v[j] - mx);
            se += __shfl_xor_sync(gmask, se, 1);
            se += __shfl_xor_sync(gmask, se, 2);
            if (sub == 0) su[r] = -(mx + __logf(se));
        }
        __syncthreads();

        // ---- column partials: value-cached single pass
        {
            float v[24];
            float mx = -3.4e38f;
#pragma unroll
            for (int i = 0; i < 24; i++) {
                if (i >= nr) break;
                v[i] = sM[(rs_ + i) * 65 + col] + su[rs_ + i];
                mx = fmaxf(mx, v[i]);
            }
            float se = 0.f;
#pragma unroll
            for (int i = 0; i < 24; i++) {
                if (i >= nr) break;
                se += __expf(v[i] - mx);
            }
            wmx[w >> 1][col] = mx;
            wse[w >> 1][col] = se;
        }
        __syncthreads();
        int par = it & 1;
        if (tid < KP) {
            float mx = fmaxf(fmaxf(wmx[0][tid], wmx[1][tid]), fmaxf(wmx[2][tid], wmx[3][tid]));
            float se = 0.f;
#pragma unroll
            for (int i = 0; i < 4; i++) se += wse[i][tid] * __expf(wmx[i][tid] - mx);
            pmx[par][tid] = mx;
            pse[par][tid] = se;
        }

        asm volatile("barrier.cluster.arrive.aligned;" ::: "memory");
        asm volatile("barrier.cluster.wait.aligned;" ::: "memory");

        if (tid < KP) {
            unsigned amx = smem_u32(&pmx[par][tid]);
            unsigned ase = smem_u32(&pse[par][tid]);
            float m[CSIZE], sv[CSIZE];
            float MX = -3.4e38f;
#pragma unroll
            for (int rk = 0; rk < CSIZE; rk++) {
                m[rk]  = dsmem_ldf(amx, rk);
                sv[rk] = dsmem_ldf(ase, rk);
                MX = fmaxf(MX, m[rk]);
            }
            float SE = 0.f;
#pragma unroll
            for (int rk = 0; rk < CSIZE; rk++) SE += sv[rk] * __expf(m[rk] - MX);
            slv[tid] = -KLF * (MX + __logf(SE));
        }
        __syncthreads();
    }

    if (tid < cn) g_up[s + r0 + tid] = su[tid];
    if (rank == 0 && tid < KP) g_lv[t * KP + tid] = slv[tid];

    // no CTA may exit while a peer might still read its smem (final combine)
    asm volatile("barrier.cluster.arrive.aligned;" ::: "memory");
    asm volatile("barrier.cluster.wait.aligned;" ::: "memory");
}

// ---------------- fused output: T (float4 coalesced) + logits -------------------
__global__ void k_out(const int* __restrict__ jt, float* __restrict__ out) {
    int idx4 = blockIdx.x * blockDim.x + threadIdx.x;   // over N*NSLOT/4
    int base = idx4 * 4;
    int n = base / NSLOT;
    int s0 = base - n * NSLOT;
    int tn = jt[n];
    int p = g_pos[n];
    float up = g_up[p];
    float e[4] = {0.f, 0.f, 0.f, 0.f};
#pragma unroll
    for (int q = 0; q < 4; q++) {
        int slot = s0 + q;
        int k = slot / NT;
        int t = slot - k * NT;
        if (t == tn) {
            float ev = __expf(g_Mp[p * KP + k] + up + g_lv[tn * KP + k]);
            e[q] = ev;
            out[n * KP + k] = __logf(ev + 1e-8f);
        }
    }
    *(float4*)&out[N * KP + base] = make_float4(e[0], e[1], e[2], e[3]);
}

__global__ void k_out_logits(const int* __restrict__ jt, float* __restrict__ out) {
    int idx = blockIdx.x * blockDim.x + threadIdx.x;   // over N*KP
    if (idx >= N * KP) return;
    int n = idx >> 6, k = idx & 63;
    int tn = jt[n];
    int p = g_pos[n];
    float e = __expf(g_Mp[p * KP + k] + g_up[p] + g_lv[tn * KP + k]);
    out[n * KP + k] = __logf(e + 1e-8f);
}

// ---------------- launch --------------------------------------------------------
extern "C" void kernel_launch(void* const* d_in, const int* in_sizes, int n_in,
                              void* d_out, int out_size) {
    const float* emb   = (const float*)d_in[0];
    const int*   jt    = (const int*)d_in[1];
    const float* W1    = (const float*)d_in[2];
    const float* b1    = (const float*)d_in[3];
    const float* proto = (const float*)d_in[4];
    float* out = (float*)d_out;
    int write_T = (out_size >= N * KP + N * NSLOT) ? 1 : 0;

    p_hist<<<NBH, 256>>>(jt);
    p_scatter<<<NBH, 256>>>(jt);

    k_gemm1<<<dim3(N / 256, H / 128), 512>>>(emb, W1, b1);
    k_gemm2<<<N / 64, 256>>>(proto);

    k_sinkhorn<<<NT * CSIZE, 256>>>();

    if (write_T) k_out<<<(N * NSLOT / 4) / 256, 256>>>(jt, out);
    else         k_out_logits<<<(N * KP) / 256, 256>>>(jt, out);
}